// round 3
// baseline (speedup 1.0000x reference)
#include <cuda_runtime.h>
#include <math.h>
#include <stdint.h>

// Problem constants
#define NB   16      // batch
#define NPTS 512     // points per sample
#define MS   4096    // m = 64*64 grid cells
#define NIT  100     // ASGD iterations
#define REGC 10.0f

// Scratch (device globals; no allocation allowed)
__device__ float g_w[NB * MS];     // beta + REG*log(b), per sample
__device__ float g_loss[NB];
__device__ float g_ot[NB];
__device__ float g_wd[NB * 8];     // per-(sample,chunk) wd partials
__device__ int   g_idx[NB * NIT];  // threefry-derived row indices

// ---------------------------------------------------------------------------
// Threefry2x32, JAX *partitionable* path (jax_threefry_partitionable=True):
//   split(key(1)=(0,1)) child i = tf2x32(k=(0,1), x=(0, i)) -> (y0, y1)
//     => k2 = child 1.
//   random_bits(k2, 32, (16,100)) [partitionable]:
//     bits[i] = y0 ^ y1 of tf2x32(k=k2, x=(0, i)),  i = 0..1599
//   randint span=512 (pow2): multiplier = (2^16 % 512)^2 % 512 = 0
//     => idx[i] = bits[i] & 511  (lower_bits only, i.e. k2 stream)
// ---------------------------------------------------------------------------
__device__ __forceinline__ uint32_t rotl32(uint32_t x, int r) {
    return (x << r) | (x >> (32 - r));
}

__device__ __forceinline__ void tf2x32(uint32_t k0, uint32_t k1,
                                       uint32_t& x0, uint32_t& x1) {
    uint32_t ks2 = 0x1BD11BDAu ^ k0 ^ k1;
    x0 += k0; x1 += k1;
#define TF_RND(r) { x0 += x1; x1 = rotl32(x1, r); x1 ^= x0; }
    TF_RND(13) TF_RND(15) TF_RND(26) TF_RND(6)
    x0 += k1;  x1 += ks2 + 1u;
    TF_RND(17) TF_RND(29) TF_RND(16) TF_RND(24)
    x0 += ks2; x1 += k0 + 2u;
    TF_RND(13) TF_RND(15) TF_RND(26) TF_RND(6)
    x0 += k0;  x1 += k1 + 3u;
    TF_RND(17) TF_RND(29) TF_RND(16) TF_RND(24)
    x0 += k1;  x1 += ks2 + 4u;
    TF_RND(13) TF_RND(15) TF_RND(26) TF_RND(6)
    x0 += ks2; x1 += k0 + 5u;
#undef TF_RND
}

__global__ void k_idx() {
    int t = blockIdx.x * blockDim.x + threadIdx.x;
    if (t >= NB * NIT) return;
    // k2 = split(key(1))[1] via foldlike split: tf over counter (0, 1)
    uint32_t c0 = 0u, c1 = 1u;
    tf2x32(0u, 1u, c0, c1);          // (c0, c1) = (y0, y1) = k2
    // lower_bits[t] = y0 ^ y1 of tf(k2, (0, t))
    uint32_t x0 = 0u, x1 = (uint32_t)t;
    tf2x32(c0, c1, x0, x1);
    g_idx[t] = (int)((x0 ^ x1) & 511u);
}

// ---------------------------------------------------------------------------
// Scan kernel: one block per sample, 1024 threads, 4 cells/thread in regs.
// ---------------------------------------------------------------------------
__device__ __forceinline__ float block_sum(float v, float* sbuf, float* bres) {
    int tid = threadIdx.x;
    #pragma unroll
    for (int o = 16; o > 0; o >>= 1) v += __shfl_xor_sync(0xffffffffu, v, o);
    if ((tid & 31) == 0) sbuf[tid >> 5] = v;
    __syncthreads();
    if (tid < 32) {
        float u = sbuf[tid];
        #pragma unroll
        for (int o = 16; o > 0; o >>= 1) u += __shfl_xor_sync(0xffffffffu, u, o);
        if (tid == 0) *bres = u;
    }
    __syncthreads();
    return *bres;
}

__global__ void __launch_bounds__(1024, 1)
k_scan(const float* __restrict__ normed, const float* __restrict__ unnormed,
       const float* __restrict__ pts) {
    const int s = blockIdx.x;
    const int tid = threadIdx.x;
    __shared__ float smx[32], ssm[32];
    __shared__ float bmax, bsum;

    const float* bp = normed   + s * MS;
    const float* up = unnormed + s * MS;
    const float* pp = pts      + s * NPTS * 2;

    float bv[4], lb[4], cur[4], ave[4], cxs[4], cys[4];
    #pragma unroll
    for (int t = 0; t < 4; t++) {
        int j = tid + t * 1024;
        bv[t] = bp[j];
        lb[t] = logf(bv[t]);
        cur[t] = 0.0f; ave[t] = 0.0f;
        cxs[t] = (float)((j & 63) * 8 + 4);
        cys[t] = (float)((j >> 6) * 8 + 4);
    }

    const float lr = 1.0f / ((1.0f / 512.0f) / REGC);   // = 5120
    const int lane = tid & 31;

    for (int k = 1; k <= NIT; k++) {
        int i = g_idx[s * NIT + (k - 1)];
        float px = pp[2 * i], py = pp[2 * i + 1];
        float px2 = px * px, py2 = py * py;

        // local z + online (max, sum-of-exp)
        float z[4];
        float mx = -INFINITY, se = 0.0f;
        #pragma unroll
        for (int t = 0; t < 4; t++) {
            float cx = cxs[t], cy = cys[t];
            float xd = (-2.0f * px) * cx + px2 + cx * cx;
            float yd = (-2.0f * py) * cy + py2 + cy * cy;
            float Mv = yd + xd;
            z[t] = (cur[t] - Mv) * (1.0f / REGC) + lb[t];
            if (z[t] > mx) { se = se * expf(mx - z[t]) + 1.0f; mx = z[t]; }
            else           { se += expf(z[t] - mx); }
        }
        // warp combine (mx, se)
        #pragma unroll
        for (int o = 16; o > 0; o >>= 1) {
            float m2 = __shfl_xor_sync(0xffffffffu, mx, o);
            float s2 = __shfl_xor_sync(0xffffffffu, se, o);
            float nm = fmaxf(mx, m2);
            se = se * expf(mx - nm) + s2 * expf(m2 - nm);
            mx = nm;
        }
        if (lane == 0) { smx[tid >> 5] = mx; ssm[tid >> 5] = se; }
        __syncthreads();
        if (tid < 32) {
            float m1 = smx[tid], s1 = ssm[tid];
            #pragma unroll
            for (int o = 16; o > 0; o >>= 1) {
                float m2 = __shfl_xor_sync(0xffffffffu, m1, o);
                float s2 = __shfl_xor_sync(0xffffffffu, s1, o);
                float nm = fmaxf(m1, m2);
                s1 = s1 * expf(m1 - nm) + s2 * expf(m2 - nm);
                m1 = nm;
            }
            if (tid == 0) { bmax = m1; bsum = s1; }
        }
        __syncthreads();
        float gmax = bmax;
        float inv  = 1.0f / bsum;
        float kf   = (float)k;
        float c    = lr / sqrtf(kf);
        float invk = 1.0f / kf;
        #pragma unroll
        for (int t = 0; t < 4; t++) {
            float khi = expf(z[t] - gmax) * inv;
            cur[t] += c * (bv[t] - khi);
            ave[t] = cur[t] * invk + (1.0f - invk) * ave[t];
        }
        // next-iteration barrier (sync#1 of next iter) protects smx/ssm/bmax reuse
    }

    // Epilogue: write w = beta + REG*log(b); reduce ot, sc, src·beta, loss
    float src[4];
    float p_ot = 0.0f, p_sc = 0.0f, p_td = 0.0f;
    #pragma unroll
    for (int t = 0; t < 4; t++) {
        int j = tid + t * 1024;
        g_w[s * MS + j] = ave[t] + REGC * lb[t];
        src[t] = up[j];
        p_ot += bv[t] * ave[t];
        p_sc += src[t];
        p_td += src[t] * ave[t];
    }
    float ot = block_sum(p_ot, smx, &bmax);
    float sc = block_sum(p_sc, smx, &bmax);
    float td = block_sum(p_td, smx, &bmax);
    float denom = sc * sc + 1e-16f;
    float q1 = sc / denom, q2 = td / denom;
    float p_ls = 0.0f;
    #pragma unroll
    for (int t = 0; t < 4; t++) p_ls += src[t] * (q1 * ave[t] - q2);
    float ls = block_sum(p_ls, smx, &bmax);
    if (tid == 0) { g_ot[s] = ot; g_loss[s] = ls; }
}

// ---------------------------------------------------------------------------
// Final phase: per row i, online softmax over j of (w_j - M_ij)/REG,
// accumulating E[M]; wd = (1/512) * sum_i E[M]_i.
// grid = (8 chunks, 16 samples), 256 threads (8 warps), warp = 8 rows.
// ---------------------------------------------------------------------------
__global__ void __launch_bounds__(256)
k_wd(const float* __restrict__ pts) {
    const int s = blockIdx.y;
    const int chunk = blockIdx.x;
    const int tid = threadIdx.x;
    __shared__ float sw[MS];
    __shared__ float warpacc[8];

    for (int j = tid; j < MS; j += 256) sw[j] = g_w[s * MS + j];
    __syncthreads();

    const int wid = tid >> 5, lane = tid & 31;
    const float* pp = pts + s * NPTS * 2;
    float acc = 0.0f;

    for (int rr = 0; rr < 8; rr++) {
        int i = chunk * 64 + wid * 8 + rr;
        float px = pp[2 * i], py = pp[2 * i + 1];
        float px2 = px * px, py2 = py * py;
        float mx = -INFINITY, se = 0.0f, st = 0.0f;
        #pragma unroll 4
        for (int it = 0; it < 128; it++) {
            int j = lane + 32 * it;
            float cx = (float)((j & 63) * 8 + 4);
            float cy = (float)((j >> 6) * 8 + 4);
            float Mv = ((-2.0f * py) * cy + py2 + cy * cy)
                     + ((-2.0f * px) * cx + px2 + cx * cx);
            float z = (sw[j] - Mv) * (1.0f / REGC);
            if (z > mx) {
                float f = expf(mx - z);
                se = se * f + 1.0f;
                st = st * f + Mv;
                mx = z;
            } else {
                float e = expf(z - mx);
                se += e;
                st += e * Mv;
            }
        }
        // lane combine (mx, se, st)
        #pragma unroll
        for (int o = 16; o > 0; o >>= 1) {
            float m2 = __shfl_xor_sync(0xffffffffu, mx, o);
            float s2 = __shfl_xor_sync(0xffffffffu, se, o);
            float t2 = __shfl_xor_sync(0xffffffffu, st, o);
            float nm = fmaxf(mx, m2);
            float f1 = expf(mx - nm), f2 = expf(m2 - nm);
            se = se * f1 + s2 * f2;
            st = st * f1 + t2 * f2;
            mx = nm;
        }
        acc += st / se;
    }
    if (lane == 0) warpacc[wid] = acc;
    __syncthreads();
    if (tid == 0) {
        float t = 0.0f;
        for (int w = 0; w < 8; w++) t += warpacc[w];
        g_wd[s * 8 + chunk] = t * (1.0f / 512.0f);
    }
}

// ---------------------------------------------------------------------------
// Deterministic fixed-order finalize: out = [loss.sum, wd.sum, ot.sum]
// ---------------------------------------------------------------------------
__global__ void k_final(float* __restrict__ out) {
    if (threadIdx.x == 0 && blockIdx.x == 0) {
        float L = 0.0f, O = 0.0f, W = 0.0f;
        for (int s = 0; s < NB; s++) { L += g_loss[s]; O += g_ot[s]; }
        for (int p = 0; p < NB * 8; p++) W += g_wd[p];
        out[0] = L; out[1] = W; out[2] = O;
    }
}

extern "C" void kernel_launch(void* const* d_in, const int* in_sizes, int n_in,
                              void* d_out, int out_size) {
    const float* normed   = (const float*)d_in[0];
    const float* unnormed = (const float*)d_in[1];
    const float* pts      = (const float*)d_in[2];
    float* out = (float*)d_out;

    k_idx<<<(NB * NIT + 255) / 256, 256>>>();
    k_scan<<<NB, 1024>>>(normed, unnormed, pts);
    dim3 g(8, NB);
    k_wd<<<g, 256>>>(pts);
    k_final<<<1, 32>>>(out);
}

// round 4
// speedup vs baseline: 2.2498x; 2.2498x over previous
#include <cuda_runtime.h>
#include <math.h>
#include <stdint.h>

// Problem constants
#define NB   16      // batch
#define NPTS 512     // points per sample
#define MS   4096    // m = 64*64 grid cells
#define NIT  100     // ASGD iterations
#define REGC 10.0f
#define NCHUNK 16    // wd chunks per sample

// Scratch (device globals; no allocation allowed)
__device__ float g_w[NB * MS];       // beta + REG*log(b), per sample
__device__ float g_loss[NB];
__device__ float g_ot[NB];
__device__ float g_wd[NB * NCHUNK]; // per-(sample,chunk) wd partials

// ---------------------------------------------------------------------------
// Threefry2x32, JAX partitionable path (verified passing in R3):
//   k2 = tf((0,1), (0,1));  idx[t] = (y0^y1 of tf(k2, (0,t))) & 511
// ---------------------------------------------------------------------------
__device__ __forceinline__ uint32_t rotl32(uint32_t x, int r) {
    return (x << r) | (x >> (32 - r));
}

__device__ __forceinline__ void tf2x32(uint32_t k0, uint32_t k1,
                                       uint32_t& x0, uint32_t& x1) {
    uint32_t ks2 = 0x1BD11BDAu ^ k0 ^ k1;
    x0 += k0; x1 += k1;
#define TF_RND(r) { x0 += x1; x1 = rotl32(x1, r); x1 ^= x0; }
    TF_RND(13) TF_RND(15) TF_RND(26) TF_RND(6)
    x0 += k1;  x1 += ks2 + 1u;
    TF_RND(17) TF_RND(29) TF_RND(16) TF_RND(24)
    x0 += ks2; x1 += k0 + 2u;
    TF_RND(13) TF_RND(15) TF_RND(26) TF_RND(6)
    x0 += k0;  x1 += k1 + 3u;
    TF_RND(17) TF_RND(29) TF_RND(16) TF_RND(24)
    x0 += k1;  x1 += ks2 + 4u;
    TF_RND(13) TF_RND(15) TF_RND(26) TF_RND(6)
    x0 += ks2; x1 += k0 + 5u;
#undef TF_RND
}

// ---------------------------------------------------------------------------
// Scan kernel: one block per sample, 512 threads, 8 cells/thread in regs.
// Two-phase softmax reduce per iter (max, then sum) -> 2 barriers/iter,
// no exp in any shuffle chain, cross-warp level redundant in all warps.
// ---------------------------------------------------------------------------
__global__ void __launch_bounds__(512, 1)
k_scan(const float* __restrict__ normed, const float* __restrict__ unnormed,
       const float* __restrict__ pts) {
    const int s   = blockIdx.x;
    const int tid = threadIdx.x;
    const int lane = tid & 31;
    const int wid  = tid >> 5;          // 0..15

    __shared__ float smx[2][16], ssm[2][16];
    __shared__ float spt[NIT * 2];      // (px,py) per iteration
    __shared__ float sred[16];
    __shared__ float sscal[4];          // epilogue broadcast

    const float* bp = normed   + s * MS;
    const float* up = unnormed + s * MS;
    const float* pp = pts      + s * NPTS * 2;

    // Fused index generation + point gather (was a separate kernel)
    if (tid < NIT) {
        uint32_t c0 = 0u, c1 = 1u;
        tf2x32(0u, 1u, c0, c1);               // k2
        uint32_t x0 = 0u, x1 = (uint32_t)(s * NIT + tid);
        tf2x32(c0, c1, x0, x1);
        int i = (int)((x0 ^ x1) & 511u);
        spt[2 * tid]     = pp[2 * i];
        spt[2 * tid + 1] = pp[2 * i + 1];
    }

    float bv[8], lb[8], cur[8], ave[8], cxs[8], cys[8], z[8];
    #pragma unroll
    for (int t = 0; t < 8; t++) {
        int j = tid + t * 512;
        bv[t] = bp[j];
        lb[t] = logf(bv[t]);
        cur[t] = 0.0f; ave[t] = 0.0f;
        cxs[t] = (float)((j & 63) * 8 + 4);
        cys[t] = (float)((j >> 6) * 8 + 4);
    }
    __syncthreads();

    const float lr = 5120.0f;   // 1 / ((1/512)/REG)
    int buf = 0;

    for (int k = 1; k <= NIT; k++) {
        float px = spt[2 * (k - 1)], py = spt[2 * k - 1];
        float px2 = px * px, py2 = py * py;

        // ---- Phase A: z + block max ----
        float mx = -INFINITY;
        #pragma unroll
        for (int t = 0; t < 8; t++) {
            float cx = cxs[t], cy = cys[t];
            float xd = (-2.0f * px) * cx + px2 + cx * cx;
            float yd = (-2.0f * py) * cy + py2 + cy * cy;
            float Mv = yd + xd;
            z[t] = (cur[t] - Mv) * (1.0f / REGC) + lb[t];
            mx = fmaxf(mx, z[t]);
        }
        #pragma unroll
        for (int o = 16; o > 0; o >>= 1)
            mx = fmaxf(mx, __shfl_xor_sync(0xffffffffu, mx, o));
        if (lane == 0) smx[buf][wid] = mx;
        __syncthreads();
        float gmax = smx[buf][lane & 15];
        #pragma unroll
        for (int o = 8; o > 0; o >>= 1)
            gmax = fmaxf(gmax, __shfl_xor_sync(0xffffffffu, gmax, o));

        // ---- Phase B: exp + block sum ----
        float e[8];
        float se = 0.0f;
        #pragma unroll
        for (int t = 0; t < 8; t++) {
            e[t] = __expf(z[t] - gmax);
            se += e[t];
        }
        #pragma unroll
        for (int o = 16; o > 0; o >>= 1)
            se += __shfl_xor_sync(0xffffffffu, se, o);
        if (lane == 0) ssm[buf][wid] = se;
        __syncthreads();
        float bs = ssm[buf][lane & 15];
        #pragma unroll
        for (int o = 8; o > 0; o >>= 1)
            bs += __shfl_xor_sync(0xffffffffu, bs, o);

        // ---- Update ----
        float inv  = 1.0f / bs;
        float kf   = (float)k;
        float c    = lr / sqrtf(kf);
        float invk = 1.0f / kf;
        #pragma unroll
        for (int t = 0; t < 8; t++) {
            float khi = e[t] * inv;
            cur[t] += c * (bv[t] - khi);
            ave[t] = cur[t] * invk + (1.0f - invk) * ave[t];
        }
        buf ^= 1;
    }

    // ---- Epilogue: w = beta + REG*log b; reduce ot, sc, td, loss ----
    float src[8];
    float p_ot = 0.0f, p_sc = 0.0f, p_td = 0.0f;
    #pragma unroll
    for (int t = 0; t < 8; t++) {
        int j = tid + t * 512;
        g_w[s * MS + j] = ave[t] + REGC * lb[t];
        src[t] = up[j];
        p_ot += bv[t] * ave[t];
        p_sc += src[t];
        p_td += src[t] * ave[t];
    }
    // three block sums (redundant cross-warp scheme)
    float vals[3] = {p_ot, p_sc, p_td};
    float res[3];
    #pragma unroll
    for (int r = 0; r < 3; r++) {
        float v = vals[r];
        #pragma unroll
        for (int o = 16; o > 0; o >>= 1)
            v += __shfl_xor_sync(0xffffffffu, v, o);
        __syncthreads();                 // protect sred reuse
        if (lane == 0) sred[wid] = v;
        __syncthreads();
        float u = sred[lane & 15];
        #pragma unroll
        for (int o = 8; o > 0; o >>= 1)
            u += __shfl_xor_sync(0xffffffffu, u, o);
        res[r] = u;
    }
    float ot = res[0], sc = res[1], td = res[2];
    float denom = sc * sc + 1e-16f;
    float q1 = sc / denom, q2 = td / denom;
    float p_ls = 0.0f;
    #pragma unroll
    for (int t = 0; t < 8; t++) p_ls += src[t] * (q1 * ave[t] - q2);
    {
        float v = p_ls;
        #pragma unroll
        for (int o = 16; o > 0; o >>= 1)
            v += __shfl_xor_sync(0xffffffffu, v, o);
        __syncthreads();
        if (lane == 0) sred[wid] = v;
        __syncthreads();
        float u = sred[lane & 15];
        #pragma unroll
        for (int o = 8; o > 0; o >>= 1)
            u += __shfl_xor_sync(0xffffffffu, u, o);
        if (tid == 0) { g_ot[s] = ot; g_loss[s] = u; }
    }
    (void)sscal;
}

// ---------------------------------------------------------------------------
// wd kernel: grid (16 chunks, 16 samples), 256 threads, warp = 4 rows.
// Per row: pass1 max of (w_j - M_ij), pass2 sum e, sum e*M.
// ---------------------------------------------------------------------------
__global__ void __launch_bounds__(256)
k_wd(const float* __restrict__ pts) {
    const int s = blockIdx.y;
    const int chunk = blockIdx.x;
    const int tid = threadIdx.x;
    const int wid = tid >> 5, lane = tid & 31;
    __shared__ float sw[MS];
    __shared__ float warpacc[8];

    for (int j = tid; j < MS; j += 256) sw[j] = g_w[s * MS + j];
    __syncthreads();

    const float* pp = pts + s * NPTS * 2;
    float acc = 0.0f;

    const float cx0 = (float)(lane * 8 + 4);
    const float cx1 = (float)((lane + 32) * 8 + 4);

    #pragma unroll
    for (int rr = 0; rr < 4; rr++) {
        int i = chunk * 32 + wid * 4 + rr;
        float px = pp[2 * i], py = pp[2 * i + 1];
        float px2 = px * px, py2 = py * py;
        float xd0 = (-2.0f * px) * cx0 + px2 + cx0 * cx0;
        float xd1 = (-2.0f * px) * cx1 + px2 + cx1 * cx1;

        // pass 1: row max of (w - M)
        float mx = -INFINITY;
        #pragma unroll 4
        for (int jy = 0; jy < 64; jy++) {
            float cy = (float)(jy * 8 + 4);
            float yd = (-2.0f * py) * cy + py2 + cy * cy;
            float v0 = sw[jy * 64 + lane]      - (yd + xd0);
            float v1 = sw[jy * 64 + lane + 32] - (yd + xd1);
            mx = fmaxf(mx, fmaxf(v0, v1));
        }
        #pragma unroll
        for (int o = 16; o > 0; o >>= 1)
            mx = fmaxf(mx, __shfl_xor_sync(0xffffffffu, mx, o));

        // pass 2: sums
        float se = 0.0f, st = 0.0f;
        #pragma unroll 4
        for (int jy = 0; jy < 64; jy++) {
            float cy = (float)(jy * 8 + 4);
            float yd = (-2.0f * py) * cy + py2 + cy * cy;
            float M0 = yd + xd0;
            float M1 = yd + xd1;
            float e0 = __expf((sw[jy * 64 + lane]      - M0 - mx) * (1.0f / REGC));
            float e1 = __expf((sw[jy * 64 + lane + 32] - M1 - mx) * (1.0f / REGC));
            se += e0 + e1;
            st += e0 * M0 + e1 * M1;
        }
        #pragma unroll
        for (int o = 16; o > 0; o >>= 1) {
            se += __shfl_xor_sync(0xffffffffu, se, o);
            st += __shfl_xor_sync(0xffffffffu, st, o);
        }
        acc += st / se;
    }
    if (lane == 0) warpacc[wid] = acc;
    __syncthreads();
    if (tid == 0) {
        float t = 0.0f;
        for (int w = 0; w < 8; w++) t += warpacc[w];
        g_wd[s * NCHUNK + chunk] = t * (1.0f / 512.0f);
    }
}

// ---------------------------------------------------------------------------
// Deterministic fixed-order finalize: out = [loss.sum, wd.sum, ot.sum]
// ---------------------------------------------------------------------------
__global__ void k_final(float* __restrict__ out) {
    if (threadIdx.x == 0 && blockIdx.x == 0) {
        float L = 0.0f, O = 0.0f, W = 0.0f;
        for (int s = 0; s < NB; s++) { L += g_loss[s]; O += g_ot[s]; }
        for (int p = 0; p < NB * NCHUNK; p++) W += g_wd[p];
        out[0] = L; out[1] = W; out[2] = O;
    }
}

extern "C" void kernel_launch(void* const* d_in, const int* in_sizes, int n_in,
                              void* d_out, int out_size) {
    const float* normed   = (const float*)d_in[0];
    const float* unnormed = (const float*)d_in[1];
    const float* pts      = (const float*)d_in[2];
    float* out = (float*)d_out;

    k_scan<<<NB, 512>>>(normed, unnormed, pts);
    dim3 g(NCHUNK, NB);
    k_wd<<<g, 256>>>(pts);
    k_final<<<1, 32>>>(out);
}